// round 1
// baseline (speedup 1.0000x reference)
#include <cuda_runtime.h>
#include <cuda_bf16.h>
#include <math.h>

// Problem constants
#define Bv 8
#define Nv 1024
#define Fv 256
#define Hv 8
#define Ev 64
#define SCALING 0.125f   // 1/sqrt(64)

// Scratch for projections (no cudaMalloc allowed)
__device__ float g_q[Hv * Bv * Nv * Ev];
__device__ float g_k[Hv * Bv * Nv * Ev];
__device__ float g_v[Hv * Bv * Nv * Ev];

// ---------------------------------------------------------------------------
// Kernel 1: projections  q/k/v[h, b*N+n, e] = sum_f x[b*N+n, f] * W[h, f, e]
// Tile: 128 rows x 64 cols (full E), K-tiles of 32. 256 threads, 8x4 micro.
// ---------------------------------------------------------------------------
__global__ __launch_bounds__(256) void proj_kernel(
    const float* __restrict__ x,
    const float* __restrict__ Wq,
    const float* __restrict__ Wk,
    const float* __restrict__ Wv)
{
    __shared__ float Xs[32][128];   // [k][row]
    __shared__ float Ws[32][64];    // [k][e]

    const int t    = threadIdx.x;
    const int row0 = blockIdx.x * 128;          // over B*N = 8192
    const int h    = blockIdx.y;
    const int z    = blockIdx.z;

    const float* W   = (z == 0) ? Wq : (z == 1) ? Wk : Wv;
    float*       out = (z == 0) ? g_q : (z == 1) ? g_k : g_v;

    const int tr = t >> 4;    // 0..15 -> rows tr*8 .. tr*8+7
    const int tc = t & 15;    // cols e = tc + 16*j

    float acc[8][4];
#pragma unroll
    for (int i = 0; i < 8; i++)
#pragma unroll
        for (int j = 0; j < 4; j++) acc[i][j] = 0.f;

    for (int k0 = 0; k0 < Fv; k0 += 32) {
        // load X tile [128][32] transposed into Xs[k][row]
#pragma unroll
        for (int c = 0; c < 4; c++) {
            int f4 = t + c * 256;            // 0..1023
            int rr = f4 >> 3;                // 0..127
            int k4 = f4 & 7;                 // 0..7
            float4 v = *reinterpret_cast<const float4*>(
                &x[(size_t)(row0 + rr) * Fv + k0 + k4 * 4]);
            Xs[k4 * 4 + 0][rr] = v.x;
            Xs[k4 * 4 + 1][rr] = v.y;
            Xs[k4 * 4 + 2][rr] = v.z;
            Xs[k4 * 4 + 3][rr] = v.w;
        }
        // load W tile [32][64]
#pragma unroll
        for (int c = 0; c < 2; c++) {
            int f4 = t + c * 256;            // 0..511
            int kk = f4 >> 4;                // 0..31
            int e4 = f4 & 15;
            *reinterpret_cast<float4*>(&Ws[kk][e4 * 4]) =
                *reinterpret_cast<const float4*>(
                    &W[(size_t)(h * Fv + k0 + kk) * Ev + e4 * 4]);
        }
        __syncthreads();

#pragma unroll
        for (int kk = 0; kk < 32; kk++) {
            float a[8], bb[4];
#pragma unroll
            for (int i = 0; i < 8; i++) a[i] = Xs[kk][tr * 8 + i];
#pragma unroll
            for (int j = 0; j < 4; j++) bb[j] = Ws[kk][tc + 16 * j];
#pragma unroll
            for (int i = 0; i < 8; i++)
#pragma unroll
                for (int j = 0; j < 4; j++) acc[i][j] += a[i] * bb[j];
        }
        __syncthreads();
    }

#pragma unroll
    for (int i = 0; i < 8; i++) {
        int r = row0 + tr * 8 + i;
#pragma unroll
        for (int j = 0; j < 4; j++) {
            out[((size_t)h * (Bv * Nv) + r) * Ev + tc + 16 * j] = acc[i][j];
        }
    }
}

// ---------------------------------------------------------------------------
// Kernel 2: fused attention per (h, b, 32-row block).
// smem: S[32][1025] score panel, Q[32][65], KV[256][65].
// ---------------------------------------------------------------------------
#define RB   32
#define MT   256
#define SSTR 1025
#define QSTR 65
#define KSTR 65
#define SMEM_FLOATS (RB * SSTR + RB * QSTR + MT * KSTR)
#define SMEM_BYTES  (SMEM_FLOATS * 4)

__global__ __launch_bounds__(256) void attn_kernel(
    float* __restrict__ attn_out,   // [H,B,N,N] (may be null)
    float* __restrict__ out)        // [B,N,H*E]
{
    extern __shared__ float smem[];
    float* S  = smem;                    // RB * SSTR
    float* Qs = S + RB * SSTR;           // RB * QSTR
    float* KV = Qs + RB * QSTR;          // MT * KSTR

    const int t    = threadIdx.x;
    const int rblk = blockIdx.x;         // 0..31
    const int b    = blockIdx.y;
    const int h    = blockIdx.z;
    const int row0 = rblk * RB;

    const float* qbase = g_q + (size_t)((h * Bv + b) * Nv) * Ev;
    const float* kbase = g_k + (size_t)((h * Bv + b) * Nv) * Ev;
    const float* vbase = g_v + (size_t)((h * Bv + b) * Nv) * Ev;

    // ---- load Q tile [32][64] ----
#pragma unroll
    for (int c = 0; c < 2; c++) {
        int f4 = t + c * 256;            // 0..511
        int rr = f4 >> 4;                // 0..31
        int e4 = f4 & 15;
        float4 v = *reinterpret_cast<const float4*>(
            &qbase[(size_t)(row0 + rr) * Ev + e4 * 4]);
        float* q = &Qs[rr * QSTR + e4 * 4];
        q[0] = v.x; q[1] = v.y; q[2] = v.z; q[3] = v.w;
    }

    const int lam = t & 31;              // lane-like index
    const int tr  = t >> 5;              // 0..7
    const int r0  = tr * 4;

    // ---- scores: S = Q K^T ----
    for (int m0 = 0; m0 < Nv; m0 += MT) {
        __syncthreads();                 // protect KV reuse / Q tile visible
        // load K tile [256][64]
#pragma unroll
        for (int c = 0; c < 16; c++) {
            int f4 = t + c * 256;        // 0..4095
            int jj = f4 >> 4;            // 0..255
            int e4 = f4 & 15;
            float4 v = *reinterpret_cast<const float4*>(
                &kbase[(size_t)(m0 + jj) * Ev + e4 * 4]);
            float* k = &KV[jj * KSTR + e4 * 4];
            k[0] = v.x; k[1] = v.y; k[2] = v.z; k[3] = v.w;
        }
        __syncthreads();

        float acc[4][8];
#pragma unroll
        for (int i = 0; i < 4; i++)
#pragma unroll
            for (int j = 0; j < 8; j++) acc[i][j] = 0.f;

#pragma unroll 4
        for (int e = 0; e < Ev; e++) {
            float qv[4], kv[8];
#pragma unroll
            for (int i = 0; i < 4; i++) qv[i] = Qs[(r0 + i) * QSTR + e];
#pragma unroll
            for (int j = 0; j < 8; j++) kv[j] = KV[(lam + 32 * j) * KSTR + e];
#pragma unroll
            for (int i = 0; i < 4; i++)
#pragma unroll
                for (int j = 0; j < 8; j++) acc[i][j] += qv[i] * kv[j];
        }

#pragma unroll
        for (int i = 0; i < 4; i++)
#pragma unroll
            for (int j = 0; j < 8; j++)
                S[(r0 + i) * SSTR + m0 + lam + 32 * j] = acc[i][j];
    }
    __syncthreads();

    // ---- softmax per row (8 threads/row) ----
    {
        const int srow = t >> 3;         // 0..31
        const int sub  = t & 7;
        float* srp = &S[srow * SSTR];

        float mx = -INFINITY;
#pragma unroll 8
        for (int k = 0; k < 128; k++) mx = fmaxf(mx, srp[sub + 8 * k]);
        mx = fmaxf(mx, __shfl_xor_sync(0xffffffffu, mx, 1));
        mx = fmaxf(mx, __shfl_xor_sync(0xffffffffu, mx, 2));
        mx = fmaxf(mx, __shfl_xor_sync(0xffffffffu, mx, 4));

        float sm = 0.f;
#pragma unroll 8
        for (int k = 0; k < 128; k++) {
            float vv = __expf(srp[sub + 8 * k] - mx);
            srp[sub + 8 * k] = vv;
            sm += vv;
        }
        sm += __shfl_xor_sync(0xffffffffu, sm, 1);
        sm += __shfl_xor_sync(0xffffffffu, sm, 2);
        sm += __shfl_xor_sync(0xffffffffu, sm, 4);
        float inv = 1.f / sm;

        if (attn_out != nullptr) {
            float* arow = attn_out +
                (((size_t)(h * Bv + b) * Nv + row0 + srow) * (size_t)Nv);
#pragma unroll 8
            for (int k = 0; k < 128; k++) {
                int m = sub + 8 * k;
                float vv = srp[m] * inv;
                srp[m] = vv;
                arow[m] = vv;
            }
        } else {
#pragma unroll 8
            for (int k = 0; k < 128; k++) {
                int m = sub + 8 * k;
                srp[m] *= inv;
            }
        }
    }

    // ---- AV: O = (attn*SCALING) @ V ----
    float oacc[4][2];
#pragma unroll
    for (int i = 0; i < 4; i++) { oacc[i][0] = 0.f; oacc[i][1] = 0.f; }

    for (int m0 = 0; m0 < Nv; m0 += MT) {
        __syncthreads();                 // protect KV reuse + S visibility
        // load V tile [256][64]
#pragma unroll
        for (int c = 0; c < 16; c++) {
            int f4 = t + c * 256;
            int jj = f4 >> 4;
            int e4 = f4 & 15;
            float4 v = *reinterpret_cast<const float4*>(
                &vbase[(size_t)(m0 + jj) * Ev + e4 * 4]);
            float* p = &KV[jj * KSTR + e4 * 4];
            p[0] = v.x; p[1] = v.y; p[2] = v.z; p[3] = v.w;
        }
        __syncthreads();

#pragma unroll 4
        for (int mm = 0; mm < MT; mm++) {
            float sv[4];
#pragma unroll
            for (int i = 0; i < 4; i++) sv[i] = S[(r0 + i) * SSTR + m0 + mm];
            float v0 = KV[mm * KSTR + lam];
            float v1 = KV[mm * KSTR + lam + 32];
#pragma unroll
            for (int i = 0; i < 4; i++) {
                oacc[i][0] += sv[i] * v0;
                oacc[i][1] += sv[i] * v1;
            }
        }
    }

    // write output: out[b][n][h*E + e]
#pragma unroll
    for (int i = 0; i < 4; i++) {
        int n = row0 + r0 + i;
        float* orow = out + ((size_t)b * Nv + n) * (Hv * Ev) + h * Ev;
        orow[lam]      = oacc[i][0] * SCALING;
        orow[lam + 32] = oacc[i][1] * SCALING;
    }
}

// ---------------------------------------------------------------------------
extern "C" void kernel_launch(void* const* d_in, const int* in_sizes, int n_in,
                              void* d_out, int out_size)
{
    const float* x  = (const float*)d_in[0];
    const float* Wq = (const float*)d_in[1];
    const float* Wk = (const float*)d_in[2];
    const float* Wv = (const float*)d_in[3];

    const size_t attn_elems = (size_t)Hv * Bv * Nv * Nv;   // 67,108,864
    float* attn = (float*)d_out;
    float* out  = (float*)d_out + attn_elems;
    if ((size_t)out_size < attn_elems + (size_t)Bv * Nv * Hv * Ev) {
        // fallback: only the projected output is expected
        attn = nullptr;
        out  = (float*)d_out;
    }

    proj_kernel<<<dim3(64, 8, 3), 256>>>(x, Wq, Wk, Wv);

    cudaFuncSetAttribute(attn_kernel,
                         cudaFuncAttributeMaxDynamicSharedMemorySize,
                         SMEM_BYTES);
    attn_kernel<<<dim3(Nv / RB, Bv, Hv), 256, SMEM_BYTES>>>(attn, out);
}

// round 2
// speedup vs baseline: 1.0004x; 1.0004x over previous
#include <cuda_runtime.h>
#include <cuda_bf16.h>
#include <math.h>

// Problem constants
#define Bv 8
#define Nv 1024
#define Fv 256
#define Hv 8
#define Ev 64
#define SCALING 0.125f   // 1/sqrt(64)

// Scratch for projections (no cudaMalloc allowed)
__device__ float g_q[Hv * Bv * Nv * Ev];
__device__ float g_k[Hv * Bv * Nv * Ev];
__device__ float g_v[Hv * Bv * Nv * Ev];

// ---------------------------------------------------------------------------
// Kernel 1: projections  q/k/v[h, b*N+n, e] = sum_f x[b*N+n, f] * W[h, f, e]
// Tile: 128 rows x 64 cols (full E), K-tiles of 32. 256 threads, 8x4 micro.
// ---------------------------------------------------------------------------
__global__ __launch_bounds__(256) void proj_kernel(
    const float* __restrict__ x,
    const float* __restrict__ Wq,
    const float* __restrict__ Wk,
    const float* __restrict__ Wv)
{
    __shared__ float Xs[32][128];   // [k][row]
    __shared__ float Ws[32][64];    // [k][e]

    const int t    = threadIdx.x;
    const int row0 = blockIdx.x * 128;          // over B*N = 8192
    const int h    = blockIdx.y;
    const int z    = blockIdx.z;

    const float* W   = (z == 0) ? Wq : (z == 1) ? Wk : Wv;
    float*       out = (z == 0) ? g_q : (z == 1) ? g_k : g_v;

    const int tr = t >> 4;    // 0..15 -> rows tr*8 .. tr*8+7
    const int tc = t & 15;    // cols e = tc + 16*j

    float acc[8][4];
#pragma unroll
    for (int i = 0; i < 8; i++)
#pragma unroll
        for (int j = 0; j < 4; j++) acc[i][j] = 0.f;

    for (int k0 = 0; k0 < Fv; k0 += 32) {
        // load X tile [128][32] transposed into Xs[k][row]
#pragma unroll
        for (int c = 0; c < 4; c++) {
            int f4 = t + c * 256;            // 0..1023
            int rr = f4 >> 3;                // 0..127
            int k4 = f4 & 7;                 // 0..7
            float4 v = *reinterpret_cast<const float4*>(
                &x[(size_t)(row0 + rr) * Fv + k0 + k4 * 4]);
            Xs[k4 * 4 + 0][rr] = v.x;
            Xs[k4 * 4 + 1][rr] = v.y;
            Xs[k4 * 4 + 2][rr] = v.z;
            Xs[k4 * 4 + 3][rr] = v.w;
        }
        // load W tile [32][64]
#pragma unroll
        for (int c = 0; c < 2; c++) {
            int f4 = t + c * 256;            // 0..511
            int kk = f4 >> 4;                // 0..31
            int e4 = f4 & 15;
            *reinterpret_cast<float4*>(&Ws[kk][e4 * 4]) =
                *reinterpret_cast<const float4*>(
                    &W[(size_t)(h * Fv + k0 + kk) * Ev + e4 * 4]);
        }
        __syncthreads();

#pragma unroll
        for (int kk = 0; kk < 32; kk++) {
            float a[8], bb[4];
#pragma unroll
            for (int i = 0; i < 8; i++) a[i] = Xs[kk][tr * 8 + i];
#pragma unroll
            for (int j = 0; j < 4; j++) bb[j] = Ws[kk][tc + 16 * j];
#pragma unroll
            for (int i = 0; i < 8; i++)
#pragma unroll
                for (int j = 0; j < 4; j++) acc[i][j] += a[i] * bb[j];
        }
        __syncthreads();
    }

#pragma unroll
    for (int i = 0; i < 8; i++) {
        int r = row0 + tr * 8 + i;
#pragma unroll
        for (int j = 0; j < 4; j++) {
            out[((size_t)h * (Bv * Nv) + r) * Ev + tc + 16 * j] = acc[i][j];
        }
    }
}

// ---------------------------------------------------------------------------
// Kernel 2: fused attention per (h, b, 32-row block).
// smem: S[32][1025] score panel, Q[32][65], KV[256][65].
// ---------------------------------------------------------------------------
#define RB   32
#define MT   256
#define SSTR 1025
#define QSTR 65
#define KSTR 65
#define SMEM_FLOATS (RB * SSTR + RB * QSTR + MT * KSTR)
#define SMEM_BYTES  (SMEM_FLOATS * 4)

__global__ __launch_bounds__(256) void attn_kernel(
    float* __restrict__ attn_out,   // [H,B,N,N] (may be null)
    float* __restrict__ out)        // [B,N,H*E]
{
    extern __shared__ float smem[];
    float* S  = smem;                    // RB * SSTR
    float* Qs = S + RB * SSTR;           // RB * QSTR
    float* KV = Qs + RB * QSTR;          // MT * KSTR

    const int t    = threadIdx.x;
    const int rblk = blockIdx.x;         // 0..31
    const int b    = blockIdx.y;
    const int h    = blockIdx.z;
    const int row0 = rblk * RB;

    const float* qbase = g_q + (size_t)((h * Bv + b) * Nv) * Ev;
    const float* kbase = g_k + (size_t)((h * Bv + b) * Nv) * Ev;
    const float* vbase = g_v + (size_t)((h * Bv + b) * Nv) * Ev;

    // ---- load Q tile [32][64] ----
#pragma unroll
    for (int c = 0; c < 2; c++) {
        int f4 = t + c * 256;            // 0..511
        int rr = f4 >> 4;                // 0..31
        int e4 = f4 & 15;
        float4 v = *reinterpret_cast<const float4*>(
            &qbase[(size_t)(row0 + rr) * Ev + e4 * 4]);
        float* q = &Qs[rr * QSTR + e4 * 4];
        q[0] = v.x; q[1] = v.y; q[2] = v.z; q[3] = v.w;
    }

    const int lam = t & 31;              // lane-like index
    const int tr  = t >> 5;              // 0..7
    const int r0  = tr * 4;

    // ---- scores: S = Q K^T ----
    for (int m0 = 0; m0 < Nv; m0 += MT) {
        __syncthreads();                 // protect KV reuse / Q tile visible
        // load K tile [256][64]
#pragma unroll
        for (int c = 0; c < 16; c++) {
            int f4 = t + c * 256;        // 0..4095
            int jj = f4 >> 4;            // 0..255
            int e4 = f4 & 15;
            float4 v = *reinterpret_cast<const float4*>(
                &kbase[(size_t)(m0 + jj) * Ev + e4 * 4]);
            float* k = &KV[jj * KSTR + e4 * 4];
            k[0] = v.x; k[1] = v.y; k[2] = v.z; k[3] = v.w;
        }
        __syncthreads();

        float acc[4][8];
#pragma unroll
        for (int i = 0; i < 4; i++)
#pragma unroll
            for (int j = 0; j < 8; j++) acc[i][j] = 0.f;

#pragma unroll 4
        for (int e = 0; e < Ev; e++) {
            float qv[4], kv[8];
#pragma unroll
            for (int i = 0; i < 4; i++) qv[i] = Qs[(r0 + i) * QSTR + e];
#pragma unroll
            for (int j = 0; j < 8; j++) kv[j] = KV[(lam + 32 * j) * KSTR + e];
#pragma unroll
            for (int i = 0; i < 4; i++)
#pragma unroll
                for (int j = 0; j < 8; j++) acc[i][j] += qv[i] * kv[j];
        }

#pragma unroll
        for (int i = 0; i < 4; i++)
#pragma unroll
            for (int j = 0; j < 8; j++)
                S[(r0 + i) * SSTR + m0 + lam + 32 * j] = acc[i][j];
    }
    __syncthreads();

    // ---- softmax per row (8 threads/row) ----
    {
        const int srow = t >> 3;         // 0..31
        const int sub  = t & 7;
        float* srp = &S[srow * SSTR];

        float mx = -INFINITY;
#pragma unroll 8
        for (int k = 0; k < 128; k++) mx = fmaxf(mx, srp[sub + 8 * k]);
        mx = fmaxf(mx, __shfl_xor_sync(0xffffffffu, mx, 1));
        mx = fmaxf(mx, __shfl_xor_sync(0xffffffffu, mx, 2));
        mx = fmaxf(mx, __shfl_xor_sync(0xffffffffu, mx, 4));

        float sm = 0.f;
#pragma unroll 8
        for (int k = 0; k < 128; k++) {
            float vv = __expf(srp[sub + 8 * k] - mx);
            srp[sub + 8 * k] = vv;
            sm += vv;
        }
        sm += __shfl_xor_sync(0xffffffffu, sm, 1);
        sm += __shfl_xor_sync(0xffffffffu, sm, 2);
        sm += __shfl_xor_sync(0xffffffffu, sm, 4);
        float inv = 1.f / sm;

        if (attn_out != nullptr) {
            float* arow = attn_out +
                (((size_t)(h * Bv + b) * Nv + row0 + srow) * (size_t)Nv);
#pragma unroll 8
            for (int k = 0; k < 128; k++) {
                int m = sub + 8 * k;
                float vv = srp[m] * inv;
                srp[m] = vv;
                arow[m] = vv;
            }
        } else {
#pragma unroll 8
            for (int k = 0; k < 128; k++) {
                int m = sub + 8 * k;
                srp[m] *= inv;
            }
        }
    }

    // ---- AV: O = (attn*SCALING) @ V ----
    float oacc[4][2];
#pragma unroll
    for (int i = 0; i < 4; i++) { oacc[i][0] = 0.f; oacc[i][1] = 0.f; }

    for (int m0 = 0; m0 < Nv; m0 += MT) {
        __syncthreads();                 // protect KV reuse + S visibility
        // load V tile [256][64]
#pragma unroll
        for (int c = 0; c < 16; c++) {
            int f4 = t + c * 256;
            int jj = f4 >> 4;
            int e4 = f4 & 15;
            float4 v = *reinterpret_cast<const float4*>(
                &vbase[(size_t)(m0 + jj) * Ev + e4 * 4]);
            float* p = &KV[jj * KSTR + e4 * 4];
            p[0] = v.x; p[1] = v.y; p[2] = v.z; p[3] = v.w;
        }
        __syncthreads();

#pragma unroll 4
        for (int mm = 0; mm < MT; mm++) {
            float sv[4];
#pragma unroll
            for (int i = 0; i < 4; i++) sv[i] = S[(r0 + i) * SSTR + m0 + mm];
            float v0 = KV[mm * KSTR + lam];
            float v1 = KV[mm * KSTR + lam + 32];
#pragma unroll
            for (int i = 0; i < 4; i++) {
                oacc[i][0] += sv[i] * v0;
                oacc[i][1] += sv[i] * v1;
            }
        }
    }

    // write output: out[b][n][h*E + e]
#pragma unroll
    for (int i = 0; i < 4; i++) {
        int n = row0 + r0 + i;
        float* orow = out + ((size_t)b * Nv + n) * (Hv * Ev) + h * Ev;
        orow[lam]      = oacc[i][0] * SCALING;
        orow[lam + 32] = oacc[i][1] * SCALING;
    }
}

// ---------------------------------------------------------------------------
extern "C" void kernel_launch(void* const* d_in, const int* in_sizes, int n_in,
                              void* d_out, int out_size)
{
    const float* x  = (const float*)d_in[0];
    const float* Wq = (const float*)d_in[1];
    const float* Wk = (const float*)d_in[2];
    const float* Wv = (const float*)d_in[3];

    const size_t attn_elems = (size_t)Hv * Bv * Nv * Nv;   // 67,108,864
    float* attn = (float*)d_out;
    float* out  = (float*)d_out + attn_elems;
    if ((size_t)out_size < attn_elems + (size_t)Bv * Nv * Hv * Ev) {
        // fallback: only the projected output is expected
        attn = nullptr;
        out  = (float*)d_out;
    }

    proj_kernel<<<dim3(64, 8, 3), 256>>>(x, Wq, Wk, Wv);

    cudaFuncSetAttribute(attn_kernel,
                         cudaFuncAttributeMaxDynamicSharedMemorySize,
                         SMEM_BYTES);
    attn_kernel<<<dim3(Nv / RB, Bv, Hv), 256, SMEM_BYTES>>>(attn, out);
}

// round 4
// speedup vs baseline: 2.2012x; 2.2003x over previous
#include <cuda_runtime.h>
#include <cuda_bf16.h>
#include <math.h>
#include <stdint.h>

#define Bv 8
#define Nv 1024
#define Fv 256
#define Hv 8
#define Ev 64
#define SCALING 0.125f

// ---------------- split-bf16 operand buffers (static scratch) ----------------
__device__ __nv_bfloat16 g_qhi[Hv * Bv * Nv * Ev];
__device__ __nv_bfloat16 g_qlo[Hv * Bv * Nv * Ev];
__device__ __nv_bfloat16 g_khi[Hv * Bv * Nv * Ev];
__device__ __nv_bfloat16 g_klo[Hv * Bv * Nv * Ev];
__device__ __nv_bfloat16 g_vthi[Hv * Bv * Ev * Nv];   // [hb][e][n] transposed
__device__ __nv_bfloat16 g_vtlo[Hv * Bv * Ev * Nv];

// ---------------- helpers ----------------
__device__ __forceinline__ uint32_t smem_to_u32(const void* p) {
    uint32_t a;
    asm("{ .reg .u64 tmp; cvta.to.shared.u64 tmp, %1; cvt.u32.u64 %0, tmp; }"
        : "=r"(a) : "l"(p));
    return a;
}

__device__ __forceinline__ void cp16(uint32_t dst, const void* src) {
    asm volatile("cp.async.cg.shared.global [%0], [%1], 16;"
                 :: "r"(dst), "l"(src));
}
#define CP_COMMIT() asm volatile("cp.async.commit_group;")
#define CP_WAIT1()  asm volatile("cp.async.wait_group 1;")
#define CP_WAIT0()  asm volatile("cp.async.wait_group 0;")

__device__ __forceinline__ void ldsm4(uint32_t* r, uint32_t addr) {
    asm volatile("ldmatrix.sync.aligned.m8n8.x4.shared.b16 {%0,%1,%2,%3}, [%4];"
                 : "=r"(r[0]), "=r"(r[1]), "=r"(r[2]), "=r"(r[3]) : "r"(addr));
}

__device__ __forceinline__ void mma_bf16(float* d, const uint32_t* a, const uint32_t* b) {
    asm volatile(
        "mma.sync.aligned.m16n8k16.row.col.f32.bf16.bf16.f32 "
        "{%0,%1,%2,%3}, {%4,%5,%6,%7}, {%8,%9}, {%0,%1,%2,%3};"
        : "+f"(d[0]), "+f"(d[1]), "+f"(d[2]), "+f"(d[3])
        : "r"(a[0]), "r"(a[1]), "r"(a[2]), "r"(a[3]), "r"(b[0]), "r"(b[1]));
}

__device__ __forceinline__ void split2(float a, float b, uint32_t& hi, uint32_t& lo) {
    __nv_bfloat162 h2 = __floats2bfloat162_rn(a, b);
    float ha = __low2float(h2), hb = __high2float(h2);
    __nv_bfloat162 l2 = __floats2bfloat162_rn(a - ha, b - hb);
    hi = *reinterpret_cast<uint32_t*>(&h2);
    lo = *reinterpret_cast<uint32_t*>(&l2);
}

// ---------------------------------------------------------------------------
// Kernel 1: projections -> split-bf16 operands (q,k row-major; v transposed)
// ---------------------------------------------------------------------------
__global__ __launch_bounds__(256) void proj_kernel(
    const float* __restrict__ x,
    const float* __restrict__ Wq,
    const float* __restrict__ Wk,
    const float* __restrict__ Wv)
{
    __shared__ float Xs[32][128];
    __shared__ float Ws[32][64];

    const int t    = threadIdx.x;
    const int row0 = blockIdx.x * 128;
    const int h    = blockIdx.y;
    const int z    = blockIdx.z;

    const float* W = (z == 0) ? Wq : (z == 1) ? Wk : Wv;

    const int tr = t >> 4;
    const int tc = t & 15;

    float acc[8][4];
#pragma unroll
    for (int i = 0; i < 8; i++)
#pragma unroll
        for (int j = 0; j < 4; j++) acc[i][j] = 0.f;

    for (int k0 = 0; k0 < Fv; k0 += 32) {
#pragma unroll
        for (int c = 0; c < 4; c++) {
            int f4 = t + c * 256;
            int rr = f4 >> 3;
            int k4 = f4 & 7;
            float4 v = *reinterpret_cast<const float4*>(
                &x[(size_t)(row0 + rr) * Fv + k0 + k4 * 4]);
            Xs[k4 * 4 + 0][rr] = v.x;
            Xs[k4 * 4 + 1][rr] = v.y;
            Xs[k4 * 4 + 2][rr] = v.z;
            Xs[k4 * 4 + 3][rr] = v.w;
        }
#pragma unroll
        for (int c = 0; c < 2; c++) {
            int f4 = t + c * 256;
            int kk = f4 >> 4;
            int e4 = f4 & 15;
            *reinterpret_cast<float4*>(&Ws[kk][e4 * 4]) =
                *reinterpret_cast<const float4*>(
                    &W[(size_t)(h * Fv + k0 + kk) * Ev + e4 * 4]);
        }
        __syncthreads();

#pragma unroll
        for (int kk = 0; kk < 32; kk++) {
            float a[8], bb[4];
#pragma unroll
            for (int i = 0; i < 8; i++) a[i] = Xs[kk][tr * 8 + i];
#pragma unroll
            for (int j = 0; j < 4; j++) bb[j] = Ws[kk][tc + 16 * j];
#pragma unroll
            for (int i = 0; i < 8; i++)
#pragma unroll
                for (int j = 0; j < 4; j++) acc[i][j] += a[i] * bb[j];
        }
        __syncthreads();
    }

#pragma unroll
    for (int i = 0; i < 8; i++) {
        int rg = row0 + tr * 8 + i;
#pragma unroll
        for (int j = 0; j < 4; j++) {
            int e = tc + 16 * j;
            float val = acc[i][j];
            __nv_bfloat16 hi16 = __float2bfloat16(val);
            __nv_bfloat16 lo16 = __float2bfloat16(val - __bfloat162float(hi16));
            if (z == 0) {
                size_t idx = ((size_t)h * 8192 + rg) * 64 + e;
                g_qhi[idx] = hi16; g_qlo[idx] = lo16;
            } else if (z == 1) {
                size_t idx = ((size_t)h * 8192 + rg) * 64 + e;
                g_khi[idx] = hi16; g_klo[idx] = lo16;
            } else {
                int bb2 = rg >> 10, nn = rg & 1023;
                size_t idx = (((size_t)h * 8 + bb2) * 64 + e) * 1024 + nn;
                g_vthi[idx] = hi16; g_vtlo[idx] = lo16;
            }
        }
    }
}

// ---------------------------------------------------------------------------
// Kernel 2: mma.sync attention.  Persistent: 128 CTAs x 4 tiles.
// Tile = 128 q-rows of one (h,b).  8 warps, each owns 16 rows.
// ---------------------------------------------------------------------------
#define KSTRE 72            // bf16 elems per K smem row (64 + 8 pad)
#define VSTRE 136           // bf16 elems per V smem row (128 + 8 pad)
#define OFF_KHI 0
#define OFF_KLO (128 * KSTRE * 2)                 // 18432
#define OFF_VHI (OFF_KLO + 128 * KSTRE * 2)       // 36864
#define OFF_VLO (OFF_VHI + 64 * VSTRE * 2)        // 54272
#define BUF_BYTES (OFF_VLO + 64 * VSTRE * 2)      // 71680
#define SMEM_TOTAL (2 * BUF_BYTES)                // 143360

__device__ __forceinline__ void prefetch_chunk(
    uint32_t sbuf,
    const __nv_bfloat16* khi, const __nv_bfloat16* klo,
    const __nv_bfloat16* vhi, const __nv_bfloat16* vlo,
    int m0, int t, bool loadV)
{
#pragma unroll
    for (int i = 0; i < 4; i++) {
        int idx = t + 256 * i;
        int row = idx >> 3, u = idx & 7;
        cp16(sbuf + OFF_KHI + row * 144 + u * 16, khi + (size_t)(m0 + row) * 64 + u * 8);
        cp16(sbuf + OFF_KLO + row * 144 + u * 16, klo + (size_t)(m0 + row) * 64 + u * 8);
    }
    if (loadV) {
#pragma unroll
        for (int i = 0; i < 4; i++) {
            int idx = t + 256 * i;
            int row = idx >> 4, u = idx & 15;
            cp16(sbuf + OFF_VHI + row * 272 + u * 16, vhi + (size_t)row * 1024 + m0 + u * 8);
            cp16(sbuf + OFF_VLO + row * 272 + u * 16, vlo + (size_t)row * 1024 + m0 + u * 8);
        }
    }
}

__device__ __forceinline__ void compute_S(
    float acc[16][4], uint32_t kb,
    const uint32_t qh[4][4], const uint32_t ql[4][4], int lane)
{
    const uint32_t khb = kb + OFF_KHI;
    const uint32_t klb = kb + OFF_KLO;
    const uint32_t rowoff = (uint32_t)((lane & 7) * 144 + (lane >> 3) * 16);
#pragma unroll
    for (int nt = 0; nt < 16; nt++) {
        uint32_t addr = (uint32_t)(8 * nt * 144) + rowoff;
        uint32_t bh[8], bl[8];
        ldsm4(bh,     khb + addr);
        ldsm4(bh + 4, khb + addr + 64);
        ldsm4(bl,     klb + addr);
        ldsm4(bl + 4, klb + addr + 64);
#pragma unroll
        for (int kk = 0; kk < 4; kk++) {
            mma_bf16(acc[nt], qh[kk], bh + 2 * kk);
            mma_bf16(acc[nt], ql[kk], bh + 2 * kk);
            mma_bf16(acc[nt], qh[kk], bl + 2 * kk);
        }
    }
}

__global__ __launch_bounds__(256) void attn_mma_kernel(
    float* __restrict__ attn, float* __restrict__ out)
{
    extern __shared__ char smem[];
    const uint32_t sb = smem_to_u32(smem);
    const int t    = threadIdx.x;
    const int w    = t >> 5;
    const int lane = t & 31;
    const int g    = lane >> 2;
    const int tq   = lane & 3;

    for (int it = 0; it < 4; it++) {
        const int tile = blockIdx.x * 4 + it;
        const int hb   = tile >> 3;
        const int qblk = tile & 7;
        const int h    = hb >> 3;
        const int b    = hb & 7;
        const int row0 = qblk * 128;

        const __nv_bfloat16* qhi = g_qhi + ((size_t)hb * 1024 + row0) * 64;
        const __nv_bfloat16* qlo = g_qlo + ((size_t)hb * 1024 + row0) * 64;
        const __nv_bfloat16* khi = g_khi + (size_t)hb * 1024 * 64;
        const __nv_bfloat16* klo = g_klo + (size_t)hb * 1024 * 64;
        const __nv_bfloat16* vhi = g_vthi + (size_t)hb * 64 * 1024;
        const __nv_bfloat16* vlo = g_vtlo + (size_t)hb * 64 * 1024;

        // ---- Q fragments (registers, reused by both passes) ----
        const int rlA = w * 16 + g;
        uint32_t qh[4][4], ql[4][4];
#pragma unroll
        for (int kk = 0; kk < 4; kk++) {
            int e0 = kk * 16 + 2 * tq;
            qh[kk][0] = *reinterpret_cast<const uint32_t*>(qhi + (size_t)rlA * 64 + e0);
            qh[kk][1] = *reinterpret_cast<const uint32_t*>(qhi + (size_t)(rlA + 8) * 64 + e0);
            qh[kk][2] = *reinterpret_cast<const uint32_t*>(qhi + (size_t)rlA * 64 + e0 + 8);
            qh[kk][3] = *reinterpret_cast<const uint32_t*>(qhi + (size_t)(rlA + 8) * 64 + e0 + 8);
            ql[kk][0] = *reinterpret_cast<const uint32_t*>(qlo + (size_t)rlA * 64 + e0);
            ql[kk][1] = *reinterpret_cast<const uint32_t*>(qlo + (size_t)(rlA + 8) * 64 + e0);
            ql[kk][2] = *reinterpret_cast<const uint32_t*>(qlo + (size_t)rlA * 64 + e0 + 8);
            ql[kk][3] = *reinterpret_cast<const uint32_t*>(qlo + (size_t)(rlA + 8) * 64 + e0 + 8);
        }

        // ================= pass A: Z = sum exp(s) =================
        float z0 = 0.f, z1 = 0.f;
        prefetch_chunk(sb, khi, klo, vhi, vlo, 0, t, false);
        CP_COMMIT();
        for (int ch = 0; ch < 8; ch++) {
            if (ch < 7) {
                prefetch_chunk(sb + ((ch + 1) & 1) * BUF_BYTES,
                               khi, klo, vhi, vlo, (ch + 1) * 128, t, false);
                CP_COMMIT();
                CP_WAIT1();
            } else {
                CP_WAIT0();
            }
            __syncthreads();

            float acc[16][4];
#pragma unroll
            for (int nt = 0; nt < 16; nt++)
#pragma unroll
                for (int q = 0; q < 4; q++) acc[nt][q] = 0.f;

            compute_S(acc, sb + (ch & 1) * BUF_BYTES, qh, ql, lane);

#pragma unroll
            for (int nt = 0; nt < 16; nt++) {
                z0 += __expf(acc[nt][0]) + __expf(acc[nt][1]);
                z1 += __expf(acc[nt][2]) + __expf(acc[nt][3]);
            }
            __syncthreads();
        }
        z0 += __shfl_xor_sync(0xffffffffu, z0, 1);
        z0 += __shfl_xor_sync(0xffffffffu, z0, 2);
        z1 += __shfl_xor_sync(0xffffffffu, z1, 1);
        z1 += __shfl_xor_sync(0xffffffffu, z1, 2);
        const float iz0 = 1.f / z0;
        const float iz1 = 1.f / z1;

        // ================= pass B: attn store + AV =================
        float oacc[8][4];
#pragma unroll
        for (int nt = 0; nt < 8; nt++)
#pragma unroll
            for (int q = 0; q < 4; q++) oacc[nt][q] = 0.f;

        float* aA = attn ? attn + ((size_t)(hb * 1024 + row0 + rlA)) * 1024 + 2 * tq : nullptr;
        float* aB = attn ? aA + 8 * 1024 : nullptr;

        prefetch_chunk(sb, khi, klo, vhi, vlo, 0, t, true);
        CP_COMMIT();
        for (int ch = 0; ch < 8; ch++) {
            if (ch < 7) {
                prefetch_chunk(sb + ((ch + 1) & 1) * BUF_BYTES,
                               khi, klo, vhi, vlo, (ch + 1) * 128, t, true);
                CP_COMMIT();
                CP_WAIT1();
            } else {
                CP_WAIT0();
            }
            __syncthreads();

            const uint32_t kb = sb + (ch & 1) * BUF_BYTES;

            float acc[16][4];
#pragma unroll
            for (int nt = 0; nt < 16; nt++)
#pragma unroll
                for (int q = 0; q < 4; q++) acc[nt][q] = 0.f;

            compute_S(acc, kb, qh, ql, lane);

            // exp, normalize, attn store, build P fragments in registers
            uint32_t ph[8][4], pl[8][4];
#pragma unroll
            for (int nt = 0; nt < 16; nt++) {
                float e0 = __expf(acc[nt][0]) * iz0;
                float e1 = __expf(acc[nt][1]) * iz0;
                float e2 = __expf(acc[nt][2]) * iz1;
                float e3 = __expf(acc[nt][3]) * iz1;
                if (aA) {
                    *reinterpret_cast<float2*>(aA + ch * 128 + 8 * nt) = make_float2(e0, e1);
                    *reinterpret_cast<float2*>(aB + ch * 128 + 8 * nt) = make_float2(e2, e3);
                }
                int jt = nt >> 1, off = (nt & 1) * 2;
                split2(e0, e1, ph[jt][off + 0], pl[jt][off + 0]);
                split2(e2, e3, ph[jt][off + 1], pl[jt][off + 1]);
            }

            // AV: O += P (m16 k128) x V (k128 n64)
            const uint32_t vhb = kb + OFF_VHI;
            const uint32_t vlb = kb + OFF_VLO;
            const uint32_t vrow = (uint32_t)((lane & 7) * 272 + (lane >> 3) * 16);
#pragma unroll
            for (int nt = 0; nt < 8; nt++) {
                uint32_t rb = (uint32_t)(8 * nt * 272) + vrow;
#pragma unroll
                for (int ks2 = 0; ks2 < 4; ks2++) {
                    uint32_t vh4[4], vl4[4];
                    ldsm4(vh4, vhb + rb + ks2 * 64);
                    ldsm4(vl4, vlb + rb + ks2 * 64);
                    mma_bf16(oacc[nt], ph[2 * ks2],     vh4);
                    mma_bf16(oacc[nt], pl[2 * ks2],     vh4);
                    mma_bf16(oacc[nt], ph[2 * ks2],     vl4);
                    mma_bf16(oacc[nt], ph[2 * ks2 + 1], vh4 + 2);
                    mma_bf16(oacc[nt], pl[2 * ks2 + 1], vh4 + 2);
                    mma_bf16(oacc[nt], ph[2 * ks2 + 1], vl4 + 2);
                }
            }
            __syncthreads();
        }

        // ---- write O ----
        float* oA = out + ((size_t)b * 1024 + row0 + rlA) * 512 + h * 64 + 2 * tq;
        float* oB = oA + 8 * 512;
#pragma unroll
        for (int nt = 0; nt < 8; nt++) {
            *reinterpret_cast<float2*>(oA + 8 * nt) =
                make_float2(oacc[nt][0] * SCALING, oacc[nt][1] * SCALING);
            *reinterpret_cast<float2*>(oB + 8 * nt) =
                make_float2(oacc[nt][2] * SCALING, oacc[nt][3] * SCALING);
        }
    }
}

// ---------------------------------------------------------------------------
extern "C" void kernel_launch(void* const* d_in, const int* in_sizes, int n_in,
                              void* d_out, int out_size)
{
    const float* x  = (const float*)d_in[0];
    const float* Wq = (const float*)d_in[1];
    const float* Wk = (const float*)d_in[2];
    const float* Wv = (const float*)d_in[3];

    const size_t attn_elems = (size_t)Hv * Bv * Nv * Nv;
    float* attn = (float*)d_out;
    float* out  = (float*)d_out + attn_elems;
    if ((size_t)out_size < attn_elems + (size_t)Bv * Nv * Hv * Ev) {
        attn = nullptr;
        out  = (float*)d_out;
    }

    proj_kernel<<<dim3(64, 8, 3), 256>>>(x, Wq, Wk, Wv);

    static int smem_set = 0;
    if (!smem_set) {
        cudaFuncSetAttribute(attn_mma_kernel,
                             cudaFuncAttributeMaxDynamicSharedMemorySize,
                             SMEM_TOTAL);
        smem_set = 1;
    }
    attn_mma_kernel<<<128, 256, SMEM_TOTAL>>>(attn, out);
}

// round 5
// speedup vs baseline: 2.8053x; 1.2744x over previous
#include <cuda_runtime.h>
#include <cuda_bf16.h>
#include <math.h>
#include <stdint.h>

#define Bv 8
#define Nv 1024
#define Fv 256
#define Hv 8
#define Ev 64
#define SCALING 0.125f

// ---------------- split-bf16 operand buffers (static scratch) ----------------
__device__ __nv_bfloat16 g_qhi[Hv * Bv * Nv * Ev];
__device__ __nv_bfloat16 g_qlo[Hv * Bv * Nv * Ev];
__device__ __nv_bfloat16 g_khi[Hv * Bv * Nv * Ev];
__device__ __nv_bfloat16 g_klo[Hv * Bv * Nv * Ev];
__device__ __nv_bfloat16 g_vthi[Hv * Bv * Ev * Nv];   // [hb][e][n] transposed
__device__ __nv_bfloat16 g_vtlo[Hv * Bv * Ev * Nv];

// split inputs for tensor-core projection
__device__ __nv_bfloat16 g_xhi[Bv * Nv * Fv];         // [8192][256]
__device__ __nv_bfloat16 g_xlo[Bv * Nv * Fv];
__device__ __nv_bfloat16 g_wthi[3 * Hv * Ev * Fv];    // [z][h][e][f]
__device__ __nv_bfloat16 g_wtlo[3 * Hv * Ev * Fv];

// ---------------- helpers ----------------
__device__ __forceinline__ uint32_t smem_to_u32(const void* p) {
    uint32_t a;
    asm("{ .reg .u64 tmp; cvta.to.shared.u64 tmp, %1; cvt.u32.u64 %0, tmp; }"
        : "=r"(a) : "l"(p));
    return a;
}

__device__ __forceinline__ void cp16(uint32_t dst, const void* src) {
    asm volatile("cp.async.cg.shared.global [%0], [%1], 16;"
                 :: "r"(dst), "l"(src));
}
#define CP_COMMIT() asm volatile("cp.async.commit_group;")
#define CP_WAIT1()  asm volatile("cp.async.wait_group 1;")
#define CP_WAIT0()  asm volatile("cp.async.wait_group 0;")

__device__ __forceinline__ void ldsm4(uint32_t* r, uint32_t addr) {
    asm volatile("ldmatrix.sync.aligned.m8n8.x4.shared.b16 {%0,%1,%2,%3}, [%4];"
                 : "=r"(r[0]), "=r"(r[1]), "=r"(r[2]), "=r"(r[3]) : "r"(addr));
}

__device__ __forceinline__ void mma_bf16(float* d, const uint32_t* a, const uint32_t* b) {
    asm volatile(
        "mma.sync.aligned.m16n8k16.row.col.f32.bf16.bf16.f32 "
        "{%0,%1,%2,%3}, {%4,%5,%6,%7}, {%8,%9}, {%0,%1,%2,%3};"
        : "+f"(d[0]), "+f"(d[1]), "+f"(d[2]), "+f"(d[3])
        : "r"(a[0]), "r"(a[1]), "r"(a[2]), "r"(a[3]), "r"(b[0]), "r"(b[1]));
}

__device__ __forceinline__ void split2(float a, float b, uint32_t& hi, uint32_t& lo) {
    __nv_bfloat162 h2 = __floats2bfloat162_rn(a, b);
    float ha = __low2float(h2), hb = __high2float(h2);
    __nv_bfloat162 l2 = __floats2bfloat162_rn(a - ha, b - hb);
    hi = *reinterpret_cast<uint32_t*>(&h2);
    lo = *reinterpret_cast<uint32_t*>(&l2);
}

// ---------------------------------------------------------------------------
// Kernel 0a: split x -> bf16 hi/lo
// ---------------------------------------------------------------------------
__global__ __launch_bounds__(256) void split_x_kernel(const float* __restrict__ x)
{
    int idx = blockIdx.x * 256 + threadIdx.x;       // float4 index, 524288 total
    float4 v = reinterpret_cast<const float4*>(x)[idx];
    uint32_t h01, l01, h23, l23;
    split2(v.x, v.y, h01, l01);
    split2(v.z, v.w, h23, l23);
    reinterpret_cast<uint2*>(g_xhi)[idx] = make_uint2(h01, h23);
    reinterpret_cast<uint2*>(g_xlo)[idx] = make_uint2(l01, l23);
}

// ---------------------------------------------------------------------------
// Kernel 0b: transpose + split W -> wt[z][h][e][f] hi/lo
// ---------------------------------------------------------------------------
__global__ __launch_bounds__(256) void split_w_kernel(
    const float* __restrict__ Wq, const float* __restrict__ Wk,
    const float* __restrict__ Wv)
{
    __shared__ float ws[64][65];
    const int t  = threadIdx.x;
    const int f0 = blockIdx.x * 64;
    const int h  = blockIdx.y;
    const int z  = blockIdx.z;
    const float* W = (z == 0) ? Wq : (z == 1) ? Wk : Wv;

    const int r    = t >> 2;      // 0..63
    const int quad = t & 3;
#pragma unroll
    for (int j = 0; j < 4; j++) {
        int e = quad * 16 + j * 4;
        float4 v = *reinterpret_cast<const float4*>(
            &W[(size_t)(h * Fv + f0 + r) * Ev + e]);
        ws[r][e + 0] = v.x; ws[r][e + 1] = v.y;
        ws[r][e + 2] = v.z; ws[r][e + 3] = v.w;
    }
    __syncthreads();

    __nv_bfloat16* whi = g_wthi + ((size_t)(z * Hv + h) * Ev + r) * Fv + f0;
    __nv_bfloat16* wlo = g_wtlo + ((size_t)(z * Hv + h) * Ev + r) * Fv + f0;
#pragma unroll
    for (int j = 0; j < 4; j++) {
        int f = quad * 16 + j * 4;
        float v0 = ws[f + 0][r], v1 = ws[f + 1][r];
        float v2 = ws[f + 2][r], v3 = ws[f + 3][r];
        uint32_t h01, l01, h23, l23;
        split2(v0, v1, h01, l01);
        split2(v2, v3, h23, l23);
        *reinterpret_cast<uint2*>(whi + f) = make_uint2(h01, h23);
        *reinterpret_cast<uint2*>(wlo + f) = make_uint2(l01, l23);
    }
}

// ---------------------------------------------------------------------------
// Kernel 1: tensor-core projection (4-term split-bf16, fp32-accurate)
// CTA = 128 rows x 64 cols, K=256 in 4 chunks, double-buffered X.
// ---------------------------------------------------------------------------
#define P_OFF_WHI 0
#define P_OFF_WLO 33792                       // 64*528
#define P_OFF_X   67584
#define P_XBUF    36864                       // (128*144)*2 (hi+lo)
#define P_OFF_XHI 0
#define P_OFF_XLO 18432
#define PROJ_SMEM (67584 + 2 * P_XBUF)        // 141312

__global__ __launch_bounds__(256) void proj_mma_kernel()
{
    extern __shared__ char smem[];
    const uint32_t sb = smem_to_u32(smem);
    const int t    = threadIdx.x;
    const int w    = t >> 5;
    const int lane = t & 31;
    const int g    = lane >> 2;
    const int tq   = lane & 3;

    const int rb = blockIdx.x;        // 64 rowblocks of 128
    const int h  = blockIdx.y;
    const int z  = blockIdx.z;
    const int row0 = rb * 128;

    const __nv_bfloat16* whi_g = g_wthi + (size_t)(z * Hv + h) * Ev * Fv;
    const __nv_bfloat16* wlo_g = g_wtlo + (size_t)(z * Hv + h) * Ev * Fv;

    // ---- load W (once) ----
#pragma unroll
    for (int i = 0; i < 8; i++) {
        int idx = t + 256 * i;            // 0..2047
        int row = idx >> 5, u = idx & 31;
        cp16(sb + P_OFF_WHI + row * 528 + u * 16, whi_g + (size_t)row * 256 + u * 8);
        cp16(sb + P_OFF_WLO + row * 528 + u * 16, wlo_g + (size_t)row * 256 + u * 8);
    }
    // ---- load X chunk 0 ----
#pragma unroll
    for (int i = 0; i < 4; i++) {
        int idx = t + 256 * i;            // 0..1023
        int row = idx >> 3, u = idx & 7;
        cp16(sb + P_OFF_X + P_OFF_XHI + row * 144 + u * 16,
             g_xhi + (size_t)(row0 + row) * 256 + u * 8);
        cp16(sb + P_OFF_X + P_OFF_XLO + row * 144 + u * 16,
             g_xlo + (size_t)(row0 + row) * 256 + u * 8);
    }
    CP_COMMIT();

    float acc[8][4];
#pragma unroll
    for (int et = 0; et < 8; et++)
#pragma unroll
        for (int q = 0; q < 4; q++) acc[et][q] = 0.f;

    for (int c = 0; c < 4; c++) {
        if (c < 3) {
            uint32_t nb = sb + P_OFF_X + ((c + 1) & 1) * P_XBUF;
#pragma unroll
            for (int i = 0; i < 4; i++) {
                int idx = t + 256 * i;
                int row = idx >> 3, u = idx & 7;
                cp16(nb + P_OFF_XHI + row * 144 + u * 16,
                     g_xhi + (size_t)(row0 + row) * 256 + (c + 1) * 64 + u * 8);
                cp16(nb + P_OFF_XLO + row * 144 + u * 16,
                     g_xlo + (size_t)(row0 + row) * 256 + (c + 1) * 64 + u * 8);
            }
            CP_COMMIT();
            CP_WAIT1();
        } else {
            CP_WAIT0();
        }
        __syncthreads();

        const uint32_t xb = sb + P_OFF_X + (c & 1) * P_XBUF;
        const uint32_t abase = (uint32_t)(w * 16 * 144 + (lane & 15) * 144 +
                                          (lane >> 4) * 16);
        uint32_t ah[4][4], al[4][4];
#pragma unroll
        for (int ks = 0; ks < 4; ks++) {
            ldsm4(ah[ks], xb + P_OFF_XHI + abase + ks * 32);
            ldsm4(al[ks], xb + P_OFF_XLO + abase + ks * 32);
        }

        const uint32_t brow = (uint32_t)((lane & 7) * 528 + (lane >> 3) * 16 +
                                         c * 128);
#pragma unroll
        for (int et = 0; et < 8; et++) {
            uint32_t bt = (uint32_t)(et * 8 * 528) + brow;
            uint32_t bh[8], bl[8];
            ldsm4(bh,     sb + P_OFF_WHI + bt);
            ldsm4(bh + 4, sb + P_OFF_WHI + bt + 64);
            ldsm4(bl,     sb + P_OFF_WLO + bt);
            ldsm4(bl + 4, sb + P_OFF_WLO + bt + 64);
#pragma unroll
            for (int ks = 0; ks < 4; ks++) {
                mma_bf16(acc[et], ah[ks], bh + 2 * ks);
                mma_bf16(acc[et], al[ks], bh + 2 * ks);
                mma_bf16(acc[et], ah[ks], bl + 2 * ks);
                mma_bf16(acc[et], al[ks], bl + 2 * ks);
            }
        }
        __syncthreads();
    }

    // ---- epilogue: split fp32 -> bf16 hi/lo and store ----
    const int r0 = row0 + w * 16 + g;     // first row of this thread
    if (z != 2) {
        __nv_bfloat16* dsthi = (z == 0) ? g_qhi : g_khi;
        __nv_bfloat16* dstlo = (z == 0) ? g_qlo : g_klo;
        size_t baseA = ((size_t)h * 8192 + r0) * 64;
        size_t baseB = ((size_t)h * 8192 + r0 + 8) * 64;
#pragma unroll
        for (int et = 0; et < 8; et++) {
            int e = et * 8 + 2 * tq;
            uint32_t hA, lA, hB, lB;
            split2(acc[et][0], acc[et][1], hA, lA);
            split2(acc[et][2], acc[et][3], hB, lB);
            *reinterpret_cast<uint32_t*>(dsthi + baseA + e) = hA;
            *reinterpret_cast<uint32_t*>(dstlo + baseA + e) = lA;
            *reinterpret_cast<uint32_t*>(dsthi + baseB + e) = hB;
            *reinterpret_cast<uint32_t*>(dstlo + baseB + e) = lB;
        }
    } else {
        int bA = r0 >> 10, nA = r0 & 1023;
        int bB = (r0 + 8) >> 10, nB = (r0 + 8) & 1023;
        size_t hbA = ((size_t)h * 8 + bA) * 64;
        size_t hbB = ((size_t)h * 8 + bB) * 64;
#pragma unroll
        for (int et = 0; et < 8; et++) {
            int e = et * 8 + 2 * tq;
#pragma unroll
            for (int q = 0; q < 4; q++) {
                float v = acc[et][q];
                int ee = e + (q & 1);
                size_t idx = (q < 2) ? (hbA + ee) * 1024 + nA
                                     : (hbB + ee) * 1024 + nB;
                __nv_bfloat16 hi = __float2bfloat16(v);
                __nv_bfloat16 lo = __float2bfloat16(v - __bfloat162float(hi));
                g_vthi[idx] = hi;
                g_vtlo[idx] = lo;
            }
        }
    }
}

// ---------------------------------------------------------------------------
// Kernel 2: mma.sync attention.  Persistent: 128 CTAs x 4 tiles.
// ---------------------------------------------------------------------------
#define OFF_KHI 0
#define OFF_KLO (128 * 144)                       // 18432
#define OFF_VHI (OFF_KLO + 128 * 144)             // 36864
#define OFF_VLO (OFF_VHI + 64 * 272)              // 54272
#define BUF_BYTES (OFF_VLO + 64 * 272)            // 71680
#define SMEM_TOTAL (2 * BUF_BYTES)                // 143360

__device__ __forceinline__ void prefetch_chunk(
    uint32_t sbuf,
    const __nv_bfloat16* khi, const __nv_bfloat16* klo,
    const __nv_bfloat16* vhi, const __nv_bfloat16* vlo,
    int m0, int t, bool loadV)
{
#pragma unroll
    for (int i = 0; i < 4; i++) {
        int idx = t + 256 * i;
        int row = idx >> 3, u = idx & 7;
        cp16(sbuf + OFF_KHI + row * 144 + u * 16, khi + (size_t)(m0 + row) * 64 + u * 8);
        cp16(sbuf + OFF_KLO + row * 144 + u * 16, klo + (size_t)(m0 + row) * 64 + u * 8);
    }
    if (loadV) {
#pragma unroll
        for (int i = 0; i < 4; i++) {
            int idx = t + 256 * i;
            int row = idx >> 4, u = idx & 15;
            cp16(sbuf + OFF_VHI + row * 272 + u * 16, vhi + (size_t)row * 1024 + m0 + u * 8);
            cp16(sbuf + OFF_VLO + row * 272 + u * 16, vlo + (size_t)row * 1024 + m0 + u * 8);
        }
    }
}

__device__ __forceinline__ void compute_S(
    float acc[16][4], uint32_t kb,
    const uint32_t qh[4][4], const uint32_t ql[4][4], int lane)
{
    const uint32_t khb = kb + OFF_KHI;
    const uint32_t klb = kb + OFF_KLO;
    const uint32_t rowoff = (uint32_t)((lane & 7) * 144 + (lane >> 3) * 16);
#pragma unroll
    for (int nt = 0; nt < 16; nt++) {
        uint32_t addr = (uint32_t)(8 * nt * 144) + rowoff;
        uint32_t bh[8], bl[8];
        ldsm4(bh,     khb + addr);
        ldsm4(bh + 4, khb + addr + 64);
        ldsm4(bl,     klb + addr);
        ldsm4(bl + 4, klb + addr + 64);
#pragma unroll
        for (int kk = 0; kk < 4; kk++) {
            mma_bf16(acc[nt], qh[kk], bh + 2 * kk);
            mma_bf16(acc[nt], ql[kk], bh + 2 * kk);
            mma_bf16(acc[nt], qh[kk], bl + 2 * kk);
        }
    }
}

__global__ __launch_bounds__(256) void attn_mma_kernel(
    float* __restrict__ attn, float* __restrict__ out)
{
    extern __shared__ char smem[];
    const uint32_t sb = smem_to_u32(smem);
    const int t    = threadIdx.x;
    const int w    = t >> 5;
    const int lane = t & 31;
    const int g    = lane >> 2;
    const int tq   = lane & 3;

    for (int it = 0; it < 4; it++) {
        const int tile = blockIdx.x * 4 + it;
        const int hb   = tile >> 3;
        const int qblk = tile & 7;
        const int h    = hb >> 3;
        const int b    = hb & 7;
        const int row0 = qblk * 128;

        const __nv_bfloat16* qhi = g_qhi + ((size_t)hb * 1024 + row0) * 64;
        const __nv_bfloat16* qlo = g_qlo + ((size_t)hb * 1024 + row0) * 64;
        const __nv_bfloat16* khi = g_khi + (size_t)hb * 1024 * 64;
        const __nv_bfloat16* klo = g_klo + (size_t)hb * 1024 * 64;
        const __nv_bfloat16* vhi = g_vthi + (size_t)hb * 64 * 1024;
        const __nv_bfloat16* vlo = g_vtlo + (size_t)hb * 64 * 1024;

        const int rlA = w * 16 + g;
        uint32_t qh[4][4], ql[4][4];
#pragma unroll
        for (int kk = 0; kk < 4; kk++) {
            int e0 = kk * 16 + 2 * tq;
            qh[kk][0] = *reinterpret_cast<const uint32_t*>(qhi + (size_t)rlA * 64 + e0);
            qh[kk][1] = *reinterpret_cast<const uint32_t*>(qhi + (size_t)(rlA + 8) * 64 + e0);
            qh[kk][2] = *reinterpret_cast<const uint32_t*>(qhi + (size_t)rlA * 64 + e0 + 8);
            qh[kk][3] = *reinterpret_cast<const uint32_t*>(qhi + (size_t)(rlA + 8) * 64 + e0 + 8);
            ql[kk][0] = *reinterpret_cast<const uint32_t*>(qlo + (size_t)rlA * 64 + e0);
            ql[kk][1] = *reinterpret_cast<const uint32_t*>(qlo + (size_t)(rlA + 8) * 64 + e0);
            ql[kk][2] = *reinterpret_cast<const uint32_t*>(qlo + (size_t)rlA * 64 + e0 + 8);
            ql[kk][3] = *reinterpret_cast<const uint32_t*>(qlo + (size_t)(rlA + 8) * 64 + e0 + 8);
        }

        // ================= pass A: Z = sum exp(s) =================
        float z0 = 0.f, z1 = 0.f;
        prefetch_chunk(sb, khi, klo, vhi, vlo, 0, t, false);
        CP_COMMIT();
        for (int ch = 0; ch < 8; ch++) {
            if (ch < 7) {
                prefetch_chunk(sb + ((ch + 1) & 1) * BUF_BYTES,
                               khi, klo, vhi, vlo, (ch + 1) * 128, t, false);
                CP_COMMIT();
                CP_WAIT1();
            } else {
                CP_WAIT0();
            }
            __syncthreads();

            float acc[16][4];
#pragma unroll
            for (int nt = 0; nt < 16; nt++)
#pragma unroll
                for (int q = 0; q < 4; q++) acc[nt][q] = 0.f;

            compute_S(acc, sb + (ch & 1) * BUF_BYTES, qh, ql, lane);

#pragma unroll
            for (int nt = 0; nt < 16; nt++) {
                z0 += __expf(acc[nt][0]) + __expf(acc[nt][1]);
                z1 += __expf(acc[nt][2]) + __expf(acc[nt][3]);
            }
            __syncthreads();
        }
        z0 += __shfl_xor_sync(0xffffffffu, z0, 1);
        z0 += __shfl_xor_sync(0xffffffffu, z0, 2);
        z1 += __shfl_xor_sync(0xffffffffu, z1, 1);
        z1 += __shfl_xor_sync(0xffffffffu, z1, 2);
        const float iz0 = 1.f / z0;
        const float iz1 = 1.f / z1;

        // ================= pass B: attn store + AV =================
        float oacc[8][4];
#pragma unroll
        for (int nt = 0; nt < 8; nt++)
#pragma unroll
            for (int q = 0; q < 4; q++) oacc[nt][q] = 0.f;

        float* aA = attn ? attn + ((size_t)(hb * 1024 + row0 + rlA)) * 1024 + 2 * tq : nullptr;
        float* aB = attn ? aA + 8 * 1024 : nullptr;

        prefetch_chunk(sb, khi, klo, vhi, vlo, 0, t, true);
        CP_COMMIT();
        for (int ch = 0; ch < 8; ch++) {
            if (ch < 7) {
                prefetch_chunk(sb + ((ch + 1) & 1) * BUF_BYTES,
                               khi, klo, vhi, vlo, (ch + 1) * 128, t, true);
                CP_COMMIT();
                CP_WAIT1();
            } else {
                CP_WAIT0();
            }
            __syncthreads();

            const uint32_t kb = sb + (ch & 1) * BUF_BYTES;

            float acc[16][4];
#pragma unroll
            for (int nt = 0; nt < 16; nt++)
#pragma unroll
                for (int q = 0; q < 4; q++) acc[nt][q] = 0.f;

            compute_S(acc, kb, qh, ql, lane);

            uint32_t ph[8][4], pl[8][4];
#pragma unroll
            for (int nt = 0; nt < 16; nt++) {
                float e0 = __expf(acc[nt][0]) * iz0;
                float e1 = __expf(acc[nt][1]) * iz0;
                float e2 = __expf(acc[nt][2]) * iz1;
                float e3 = __expf(acc[nt][3]) * iz1;
                if (aA) {
                    *reinterpret_cast<float2*>(aA + ch * 128 + 8 * nt) = make_float2(e0, e1);
                    *reinterpret_cast<float2*>(aB + ch * 128 + 8 * nt) = make_float2(e2, e3);
                }
                int jt = nt >> 1, off = (nt & 1) * 2;
                split2(e0, e1, ph[jt][off + 0], pl[jt][off + 0]);
                split2(e2, e3, ph[jt][off + 1], pl[jt][off + 1]);
            }

            const uint32_t vhb = kb + OFF_VHI;
            const uint32_t vlb = kb + OFF_VLO;
            const uint32_t vrow = (uint32_t)((lane & 7) * 272 + (lane >> 3) * 16);
#pragma unroll
            for (int nt = 0; nt < 8; nt++) {
                uint32_t rb2 = (uint32_t)(8 * nt * 272) + vrow;
#pragma unroll
                for (int ks2 = 0; ks2 < 4; ks2++) {
                    uint32_t vh4[4], vl4[4];
                    ldsm4(vh4, vhb + rb2 + ks2 * 64);
                    ldsm4(vl4, vlb + rb2 + ks2 * 64);
                    mma_bf16(oacc[nt], ph[2 * ks2],     vh4);
                    mma_bf16(oacc[nt], pl[2 * ks2],     vh4);
                    mma_bf16(oacc[nt], ph[2 * ks2],     vl4);
                    mma_bf16(oacc[nt], ph[2 * ks2 + 1], vh4 + 2);
                    mma_bf16(oacc[nt], pl[2 * ks2 + 1], vh4 + 2);
                    mma_bf16(oacc[nt], ph[2 * ks2 + 1], vl4 + 2);
                }
            }
            __syncthreads();
        }

        float* oA = out + ((size_t)b * 1024 + row0 + rlA) * 512 + h * 64 + 2 * tq;
        float* oB = oA + 8 * 512;
#pragma unroll
        for (int nt = 0; nt < 8; nt++) {
            *reinterpret_cast<float2*>(oA + 8 * nt) =
                make_float2(oacc[nt][0] * SCALING, oacc[nt][1] * SCALING);
            *reinterpret_cast<float2*>(oB + 8 * nt) =
                make_float2(oacc[nt][2] * SCALING, oacc[nt][3] * SCALING);
        }
    }
}

// ---------------------------------------------------------------------------
extern "C" void kernel_launch(void* const* d_in, const int* in_sizes, int n_in,
                              void* d_out, int out_size)
{
    const float* x  = (const float*)d_in[0];
    const float* Wq = (const float*)d_in[1];
    const float* Wk = (const float*)d_in[2];
    const float* Wv = (const float*)d_in[3];

    const size_t attn_elems = (size_t)Hv * Bv * Nv * Nv;
    float* attn = (float*)d_out;
    float* out  = (float*)d_out + attn_elems;
    if ((size_t)out_size < attn_elems + (size_t)Bv * Nv * Hv * Ev) {
        attn = nullptr;
        out  = (float*)d_out;
    }

    cudaFuncSetAttribute(proj_mma_kernel,
                         cudaFuncAttributeMaxDynamicSharedMemorySize, PROJ_SMEM);
    cudaFuncSetAttribute(attn_mma_kernel,
                         cudaFuncAttributeMaxDynamicSharedMemorySize, SMEM_TOTAL);

    split_x_kernel<<<2048, 256>>>(x);
    split_w_kernel<<<dim3(4, 8, 3), 256>>>(Wq, Wk, Wv);
    proj_mma_kernel<<<dim3(64, 8, 3), 256, PROJ_SMEM>>>();
    attn_mma_kernel<<<128, 256, SMEM_TOTAL>>>(attn, out);
}